// round 16
// baseline (speedup 1.0000x reference)
#include <cuda_runtime.h>
#include <math.h>
#include <stdint.h>

// Problem constants
#define B_SZ   4
#define S_LEN  1024
#define D_DIM  1024
#define H_N    16
#define DKH    64
#define DF_DIM 4096
#define NROWS  (B_SZ * S_LEN)         // 4096
#define TOPK   307                    // int(1024 * 0.3)

// ---------------------------------------------------------------------------
// Scratch (static device globals; no runtime allocation allowed)
// ---------------------------------------------------------------------------
__device__ float g_h  [NROWS * D_DIM];     // LN output (unrounded, for Q/K)
__device__ float g_hr [NROWS * D_DIM];     // tf32-rounded LN output
__device__ float g_q  [NROWS * D_DIM];
__device__ float g_k  [NROWS * D_DIM];
__device__ float g_v  [NROWS * D_DIM];
__device__ float g_ctx[NROWS * D_DIM];
__device__ float g_x1 [NROWS * D_DIM];
__device__ float g_f1 [NROWS * DF_DIM];
__device__ float g_f2 [NROWS * DF_DIM];
__device__ float g_wv_r[D_DIM * D_DIM];
__device__ float g_wo_r[D_DIM * D_DIM];
__device__ float g_w1_r[DF_DIM * D_DIM];
__device__ float g_wm_r[DF_DIM * DF_DIM];
__device__ float g_w2_r[D_DIM * DF_DIM];
__device__ float g_attn_fb[B_SZ * H_N * S_LEN * S_LEN];

__device__ __forceinline__ float gelu_f(float x) {
    return 0.5f * x * (1.0f + erff(x * 0.70710678118654752440f));
}

__device__ __forceinline__ float tf32f(float f) {
    unsigned r;
    asm("cvt.rna.tf32.f32 %0, %1;" : "=r"(r) : "f"(f));
    return __uint_as_float(r);
}

// ---------------------------------------------------------------------------
// Elementwise tf32 rounding (weights pre-pass). n multiple of 4.
// ---------------------------------------------------------------------------
__global__ __launch_bounds__(256) void round_kernel(const float* __restrict__ src,
                                                    float* __restrict__ dst, int n4) {
    int i = blockIdx.x * 256 + threadIdx.x;
    int stride = gridDim.x * 256;
    for (; i < n4; i += stride) {
        float4 v = ((const float4*)src)[i];
        v.x = tf32f(v.x); v.y = tf32f(v.y);
        v.z = tf32f(v.z); v.w = tf32f(v.w);
        ((float4*)dst)[i] = v;
    }
}

// ---------------------------------------------------------------------------
// LayerNorm: one block per row of 1024. Optional unrounded and tf32-rounded
// outputs (either may be null).
// ---------------------------------------------------------------------------
__global__ __launch_bounds__(256) void ln_kernel(const float* __restrict__ x,
                                                 const float* __restrict__ g,
                                                 const float* __restrict__ b,
                                                 float* __restrict__ out,
                                                 float* __restrict__ out_r) {
    __shared__ float rs[256], rq[256];
    int row = blockIdx.x, tid = threadIdx.x;
    const float4* px = (const float4*)(x + (size_t)row * D_DIM);
    float4 v = px[tid];
    float s = v.x + v.y + v.z + v.w;
    float q = v.x*v.x + v.y*v.y + v.z*v.z + v.w*v.w;
    rs[tid] = s; rq[tid] = q;
    __syncthreads();
    for (int st = 128; st > 0; st >>= 1) {
        if (tid < st) { rs[tid] += rs[tid+st]; rq[tid] += rq[tid+st]; }
        __syncthreads();
    }
    float mu  = rs[0] * (1.0f / D_DIM);
    float var = rq[0] * (1.0f / D_DIM) - mu * mu;
    float rstd = rsqrtf(var + 1e-5f);
    float4 gg = ((const float4*)g)[tid];
    float4 bb = ((const float4*)b)[tid];
    float4 o;
    o.x = (v.x - mu) * rstd * gg.x + bb.x;
    o.y = (v.y - mu) * rstd * gg.y + bb.y;
    o.z = (v.z - mu) * rstd * gg.z + bb.z;
    o.w = (v.w - mu) * rstd * gg.w + bb.w;
    if (out)
        ((float4*)(out + (size_t)row * D_DIM))[tid] = o;
    if (out_r) {
        float4 r;
        r.x = tf32f(o.x); r.y = tf32f(o.y);
        r.z = tf32f(o.z); r.w = tf32f(o.w);
        ((float4*)(out_r + (size_t)row * D_DIM))[tid] = r;
    }
}

// ---------------------------------------------------------------------------
// fp32 SGEMM NT (Q, K, per-head scores — protects top-k selection; R15 proved
// tf32 here flips selections and blows up the attn output error)
// ---------------------------------------------------------------------------
template<int MODE, bool HEAD>
__global__ __launch_bounds__(256) void sgemm_nt(const float* __restrict__ A,
                                                const float* __restrict__ B,
                                                const float* __restrict__ bias,
                                                const float* __restrict__ R,
                                                float* __restrict__ C,
                                                int K, int lda, int ldb, int ldc,
                                                float alpha, long strideC) {
    __shared__ float As[2][16][132];
    __shared__ float Bs[2][16][132];
    int tid = threadIdx.x;

    const float* Ab = A + (size_t)blockIdx.y * 128 * lda;
    const float* Bb = B + (size_t)blockIdx.x * 128 * ldb;
    float* Cb = C;
    if (HEAD) {
        int z = blockIdx.z;
        size_t off = (size_t)(z >> 4) * (S_LEN * D_DIM) + (size_t)(z & 15) * DKH;
        Ab += off; Bb += off;
        Cb += (size_t)z * strideC;
    }

    int tx = tid & 15, ty = tid >> 4;
    int lr = tid >> 2;
    int lc = (tid & 3) << 2;

    float acc[8][8];
#pragma unroll
    for (int i = 0; i < 8; i++)
#pragma unroll
        for (int j = 0; j < 8; j++) acc[i][j] = 0.0f;

#pragma unroll
    for (int r = 0; r < 2; r++) {
        int row = lr + r * 64;
        float4 va = *(const float4*)(Ab + (size_t)row * lda + lc);
        As[0][lc+0][row] = va.x; As[0][lc+1][row] = va.y;
        As[0][lc+2][row] = va.z; As[0][lc+3][row] = va.w;
        float4 vb = *(const float4*)(Bb + (size_t)row * ldb + lc);
        Bs[0][lc+0][row] = vb.x; Bs[0][lc+1][row] = vb.y;
        Bs[0][lc+2][row] = vb.z; Bs[0][lc+3][row] = vb.w;
    }
    __syncthreads();

    int buf = 0;
    for (int k0 = 0; k0 < K; k0 += 16) {
        float4 pa[2], pb[2];
        bool more = (k0 + 16 < K);
        if (more) {
#pragma unroll
            for (int r = 0; r < 2; r++) {
                int row = lr + r * 64;
                pa[r] = *(const float4*)(Ab + (size_t)row * lda + (k0 + 16) + lc);
                pb[r] = *(const float4*)(Bb + (size_t)row * ldb + (k0 + 16) + lc);
            }
        }
#pragma unroll
        for (int k = 0; k < 16; k++) {
            float4 a0 = *(const float4*)(&As[buf][k][ty * 8]);
            float4 a1 = *(const float4*)(&As[buf][k][ty * 8 + 4]);
            float4 b0 = *(const float4*)(&Bs[buf][k][tx * 8]);
            float4 b1 = *(const float4*)(&Bs[buf][k][tx * 8 + 4]);
            float ra[8] = {a0.x, a0.y, a0.z, a0.w, a1.x, a1.y, a1.z, a1.w};
            float rb[8] = {b0.x, b0.y, b0.z, b0.w, b1.x, b1.y, b1.z, b1.w};
#pragma unroll
            for (int i = 0; i < 8; i++)
#pragma unroll
                for (int j = 0; j < 8; j++)
                    acc[i][j] = fmaf(ra[i], rb[j], acc[i][j]);
        }
        if (more) {
            int nb = buf ^ 1;
#pragma unroll
            for (int r = 0; r < 2; r++) {
                int row = lr + r * 64;
                As[nb][lc+0][row] = pa[r].x; As[nb][lc+1][row] = pa[r].y;
                As[nb][lc+2][row] = pa[r].z; As[nb][lc+3][row] = pa[r].w;
                Bs[nb][lc+0][row] = pb[r].x; Bs[nb][lc+1][row] = pb[r].y;
                Bs[nb][lc+2][row] = pb[r].z; Bs[nb][lc+3][row] = pb[r].w;
            }
        }
        __syncthreads();
        buf ^= 1;
    }

#pragma unroll
    for (int i = 0; i < 8; i++) {
        size_t m = (size_t)blockIdx.y * 128 + ty * 8 + i;
#pragma unroll
        for (int j4 = 0; j4 < 8; j4 += 4) {
            int n = blockIdx.x * 128 + tx * 8 + j4;
            float4 v;
            v.x = acc[i][j4+0] * alpha;
            v.y = acc[i][j4+1] * alpha;
            v.z = acc[i][j4+2] * alpha;
            v.w = acc[i][j4+3] * alpha;
            if (bias != nullptr) {
                float4 bb = *(const float4*)(bias + n);
                v.x += bb.x; v.y += bb.y; v.z += bb.z; v.w += bb.w;
            }
            if (MODE == 1) {
                v.x = gelu_f(v.x); v.y = gelu_f(v.y);
                v.z = gelu_f(v.z); v.w = gelu_f(v.w);
            }
            if (MODE == 2) {
                float4 rr = *(const float4*)(R + m * ldc + n);
                v.x += rr.x; v.y += rr.y; v.z += rr.z; v.w += rr.w;
            }
            *(float4*)(Cb + m * ldc + n) = v;
        }
    }
}

// ---------------------------------------------------------------------------
// TF32 tensor-core GEMM NT, cp.async 3-stage pipeline.
// Inputs A and B MUST already be tf32-rounded (cvt.rna applied by producer).
// Block tile 128x256x32, 8 warps (2m x 4n), warp tile 64x64, mma.m16n8k8.
// Per k-group a warp does 32 LDS + 32 MMA (1:1) — double the arithmetic per
// issued load vs the old 64x32 warp tile.
// smem: row-major 32-float rows with 16B-chunk XOR swizzle c^(row&7).
// MODE: 0 plain(+bias), 1 GELU+bias stored tf32-rounded, 2 +bias +residual R
// Requires M%128==0, N%256==0, K%32==0, K>=64.
// ---------------------------------------------------------------------------
#define TG_ASZ   (128 * 32)            // A floats per stage
#define TG_BSZ   (256 * 32)            // B floats per stage
#define TG_STAGE (TG_ASZ + TG_BSZ)     // 12288 floats
#define TG_SMEM  (3 * TG_STAGE * 4)    // 147456 bytes (144 KB)

template<int MODE>
__global__ __launch_bounds__(256, 1) void tgemm_nt(const float* __restrict__ A,
                                                   const float* __restrict__ B,
                                                   const float* __restrict__ bias,
                                                   const float* __restrict__ R,
                                                   float* __restrict__ C,
                                                   int K, int lda, int ldb, int ldc) {
    extern __shared__ float sm[];

    int tid  = threadIdx.x;
    int lane = tid & 31;
    int warp = tid >> 5;
    int wm   = warp >> 2;      // 0..1 -> 64-row band
    int wn   = warp & 3;       // 0..3 -> 64-col band
    int rowi = lane >> 2;      // 0..7
    int kq   = lane & 3;       // 0..3

    const float* Ab = A + (size_t)blockIdx.y * 128 * lda;
    const float* Bb = B + (size_t)blockIdx.x * 256 * ldb;

    int lr = tid >> 3;   // 0..31 : load row base
    int lc = tid & 7;    // chunk 0..7

    // hoisted fragment base offsets (element index of [row][kq] within stage)
    int aoff[4], boff[8];
#pragma unroll
    for (int mt = 0; mt < 4; mt++) aoff[mt] = (wm * 64 + mt * 16 + rowi) * 32 + kq;
#pragma unroll
    for (int nt = 0; nt < 8; nt++) boff[nt] = (wn * 64 + nt * 8 + rowi) * 32 + kq;

    float acc[4][8][4];
#pragma unroll
    for (int mt = 0; mt < 4; mt++)
#pragma unroll
        for (int nt = 0; nt < 8; nt++)
#pragma unroll
            for (int r = 0; r < 4; r++) acc[mt][nt][r] = 0.0f;

    auto issue = [&](int kt, int st) {
        float* sA = sm + st * TG_STAGE;
        float* sB = sA + TG_ASZ;
#pragma unroll
        for (int i = 0; i < 4; i++) {
            int row  = lr + i * 32;
            int sidx = row * 32 + ((lc ^ (row & 7)) << 2);
            const float* gA = Ab + (size_t)row * lda + kt * 32 + lc * 4;
            unsigned sa = (unsigned)__cvta_generic_to_shared(sA + sidx);
            asm volatile("cp.async.cg.shared.global [%0], [%1], 16;"
                         :: "r"(sa), "l"(gA));
        }
#pragma unroll
        for (int i = 0; i < 8; i++) {
            int row  = lr + i * 32;
            int sidx = row * 32 + ((lc ^ (row & 7)) << 2);
            const float* gB = Bb + (size_t)row * ldb + kt * 32 + lc * 4;
            unsigned sb = (unsigned)__cvta_generic_to_shared(sB + sidx);
            asm volatile("cp.async.cg.shared.global [%0], [%1], 16;"
                         :: "r"(sb), "l"(gB));
        }
        asm volatile("cp.async.commit_group;");
    };

    int NT = K >> 5;
    issue(0, 0);
    issue(1, 1);

    for (int it = 0; it < NT; it++) {
        if (it + 1 < NT) asm volatile("cp.async.wait_group 1;");
        else             asm volatile("cp.async.wait_group 0;");
        __syncthreads();
        if (it + 2 < NT) issue(it + 2, (it + 2) % 3);

        const unsigned* sA = (const unsigned*)(sm + (it % 3) * TG_STAGE);
        const unsigned* sB = sA + TG_ASZ;

#pragma unroll
        for (int g = 0; g < 4; g++) {
            int sw0 = (((g << 1))     ^ rowi) << 2;
            int sw1 = (((g << 1) | 1) ^ rowi) << 2;
            unsigned af[4][4];
#pragma unroll
            for (int mt = 0; mt < 4; mt++) {
                af[mt][0] = sA[aoff[mt] + sw0];
                af[mt][1] = sA[aoff[mt] + 256 + sw0];
                af[mt][2] = sA[aoff[mt] + sw1];
                af[mt][3] = sA[aoff[mt] + 256 + sw1];
            }
            unsigned bf[8][2];
#pragma unroll
            for (int nt = 0; nt < 8; nt++) {
                bf[nt][0] = sB[boff[nt] + sw0];
                bf[nt][1] = sB[boff[nt] + sw1];
            }
#pragma unroll
            for (int mt = 0; mt < 4; mt++)
#pragma unroll
                for (int nt = 0; nt < 8; nt++)
                    asm volatile(
                        "mma.sync.aligned.m16n8k8.row.col.f32.tf32.tf32.f32 "
                        "{%0,%1,%2,%3}, {%4,%5,%6,%7}, {%8,%9}, {%0,%1,%2,%3};"
                        : "+f"(acc[mt][nt][0]), "+f"(acc[mt][nt][1]),
                          "+f"(acc[mt][nt][2]), "+f"(acc[mt][nt][3])
                        : "r"(af[mt][0]), "r"(af[mt][1]), "r"(af[mt][2]), "r"(af[mt][3]),
                          "r"(bf[nt][0]), "r"(bf[nt][1]));
        }
    }

    // ---- epilogue ----
#pragma unroll
    for (int mt = 0; mt < 4; mt++) {
#pragma unroll
        for (int rr = 0; rr < 2; rr++) {
            size_t m = (size_t)blockIdx.y * 128 + wm * 64 + mt * 16 + rowi + rr * 8;
#pragma unroll
            for (int nt = 0; nt < 8; nt++) {
                int n = blockIdx.x * 256 + wn * 64 + nt * 8 + kq * 2;
                float v0 = acc[mt][nt][rr * 2 + 0];
                float v1 = acc[mt][nt][rr * 2 + 1];
                if (bias != nullptr) {
                    float2 bb = *(const float2*)(bias + n);
                    v0 += bb.x; v1 += bb.y;
                }
                if (MODE == 1) {
                    v0 = tf32f(gelu_f(v0)); v1 = tf32f(gelu_f(v1));
                }
                if (MODE == 2) {
                    float2 rv = *(const float2*)(R + m * ldc + n);
                    v0 += rv.x; v1 += rv.y;
                }
                float2 o; o.x = v0; o.y = v1;
                *(float2*)(C + m * ldc + n) = o;
            }
        }
    }
}

// ---------------------------------------------------------------------------
// Exact top-k(307) + softmax per row of 1024, in place.
// ---------------------------------------------------------------------------
__global__ __launch_bounds__(256) void topk_softmax_kernel(float* __restrict__ attn) {
    __shared__ float vals[1024];
    __shared__ unsigned int keys[1024];
    __shared__ unsigned int hist[256];
    __shared__ unsigned int sufs[256];
    __shared__ unsigned int wsum[8];
    __shared__ int tie_idx[1024];
    __shared__ unsigned char keep[1024];
    __shared__ float red[256];
    __shared__ int s_bsel, s_rsub, s_tcnt;

    int tid  = threadIdx.x;
    int lane = tid & 31;
    int wid  = tid >> 5;
    float* p = attn + (size_t)blockIdx.x * 1024;

    for (int i = tid; i < 1024; i += 256) {
        float v = p[i];
        vals[i] = v;
        unsigned u = __float_as_uint(v);
        keys[i] = (u & 0x80000000u) ? ~u : (u | 0x80000000u);
    }
    __syncthreads();

    unsigned prefix = 0u, pmask = 0u;
    int r = TOPK;
    for (int shift = 24; shift >= 0; shift -= 8) {
        hist[tid] = 0u;
        __syncthreads();
        for (int i = tid; i < 1024; i += 256) {
            unsigned kk = keys[i];
            if ((kk & pmask) == prefix) atomicAdd(&hist[(kk >> shift) & 0xFFu], 1u);
        }
        __syncthreads();

        unsigned v = hist[tid];
#pragma unroll
        for (int d = 1; d < 32; d <<= 1) {
            unsigned t = __shfl_down_sync(0xFFFFFFFFu, v, d);
            if (lane + d < 32) v += t;
        }
        if (lane == 0) wsum[wid] = v;
        __syncthreads();
        unsigned add = 0;
#pragma unroll
        for (int w = 0; w < 8; w++)
            if (w > wid) add += wsum[w];
        v += add;
        sufs[tid] = v;
        __syncthreads();

        unsigned cum  = sufs[tid];
        unsigned cumn = (tid < 255) ? sufs[tid + 1] : 0u;
        if ((int)cum >= r && (int)cumn < r) { s_bsel = tid; s_rsub = (int)cumn; }
        __syncthreads();
        prefix |= ((unsigned)s_bsel) << shift;
        pmask  |= (0xFFu << shift);
        r -= s_rsub;
        __syncthreads();
    }
    unsigned tk = prefix;

    if (tid == 0) s_tcnt = 0;
    __syncthreads();
    for (int i = tid; i < 1024; i += 256) {
        unsigned kk = keys[i];
        unsigned char kp = (kk > tk) ? (unsigned char)1 : (unsigned char)0;
        if (kk == tk) { int pos = atomicAdd(&s_tcnt, 1); tie_idx[pos] = i; }
        keep[i] = kp;
    }
    __syncthreads();
    int tc = s_tcnt;
    for (int j = tid; j < tc; j += 256) {
        int myi = tie_idx[j];
        int rank = 0;
        for (int l = 0; l < tc; l++) rank += (tie_idx[l] < myi) ? 1 : 0;
        if (rank < r) keep[myi] = 1;
    }
    __syncthreads();

    float lm = -3.4e38f;
    for (int i = tid; i < 1024; i += 256)
        if (keep[i]) lm = fmaxf(lm, vals[i]);
    red[tid] = lm;
    __syncthreads();
    for (int st = 128; st > 0; st >>= 1) {
        if (tid < st) red[tid] = fmaxf(red[tid], red[tid + st]);
        __syncthreads();
    }
    float mx = red[0];
    __syncthreads();

    float ls = 0.0f;
    for (int i = tid; i < 1024; i += 256) {
        float e = keep[i] ? expf(vals[i] - mx) : 0.0f;
        vals[i] = e;
        ls += e;
    }
    red[tid] = ls;
    __syncthreads();
    for (int st = 128; st > 0; st >>= 1) {
        if (tid < st) red[tid] += red[tid + st];
        __syncthreads();
    }
    float inv = 1.0f / red[0];
    __syncthreads();
    for (int i = tid; i < 1024; i += 256) p[i] = vals[i] * inv;
}

// ---------------------------------------------------------------------------
// ctx = attn @ V per head (fp32). Stores tf32-rounded ctx — only consumer is
// the Wo tf32 GEMM (bit-identical to rounding at fragment load).
// ---------------------------------------------------------------------------
__global__ __launch_bounds__(256) void attn_v_kernel(const float* __restrict__ attn,
                                                     const float* __restrict__ V,
                                                     float* __restrict__ ctx) {
    __shared__ float As[128][33];
    __shared__ float Bs[32][68];
    int tid = threadIdx.x;
    int z = blockIdx.y;
    int b = z >> 4, h = z & 15;
    const float* Ab = attn + (size_t)z * (S_LEN * S_LEN) + (size_t)blockIdx.x * 128 * S_LEN;
    const float* Vb = V + (size_t)b * (S_LEN * D_DIM) + h * DKH;
    int tx = tid & 15, ty = tid >> 4;

    float acc[8][4];
#pragma unroll
    for (int i = 0; i < 8; i++)
#pragma unroll
        for (int j = 0; j < 4; j++) acc[i][j] = 0.0f;

    for (int k0 = 0; k0 < S_LEN; k0 += 32) {
#pragma unroll
        for (int r2 = 0; r2 < 4; r2++) {
            int row = r2 * 32 + (tid >> 3);
            int c4 = (tid & 7) << 2;
            float4 v = *(const float4*)(Ab + (size_t)row * S_LEN + k0 + c4);
            As[row][c4+0] = v.x; As[row][c4+1] = v.y;
            As[row][c4+2] = v.z; As[row][c4+3] = v.w;
        }
#pragma unroll
        for (int r2 = 0; r2 < 2; r2++) {
            int row = r2 * 16 + (tid >> 4);
            int c4 = (tid & 15) << 2;
            float4 v = *(const float4*)(Vb + (size_t)(k0 + row) * D_DIM + c4);
            Bs[row][c4+0] = v.x; Bs[row][c4+1] = v.y;
            Bs[row][c4+2] = v.z; Bs[row][c4+3] = v.w;
        }
        __syncthreads();
#pragma unroll
        for (int k = 0; k < 32; k++) {
            float ra[8];
#pragma unroll
            for (int i = 0; i < 8; i++) ra[i] = As[ty * 8 + i][k];
            float rb0 = Bs[k][tx*4+0], rb1 = Bs[k][tx*4+1];
            float rb2 = Bs[k][tx*4+2], rb3 = Bs[k][tx*4+3];
#pragma unroll
            for (int i = 0; i < 8; i++) {
                acc[i][0] = fmaf(ra[i], rb0, acc[i][0]);
                acc[i][1] = fmaf(ra[i], rb1, acc[i][1]);
                acc[i][2] = fmaf(ra[i], rb2, acc[i][2]);
                acc[i][3] = fmaf(ra[i], rb3, acc[i][3]);
            }
        }
        __syncthreads();
    }
#pragma unroll
    for (int i = 0; i < 8; i++) {
        size_t row = (size_t)b * S_LEN + (size_t)blockIdx.x * 128 + ty * 8 + i;
        float4 v;
        v.x = tf32f(acc[i][0]); v.y = tf32f(acc[i][1]);
        v.z = tf32f(acc[i][2]); v.w = tf32f(acc[i][3]);
        *(float4*)(ctx + row * D_DIM + h * DKH + tx * 4) = v;
    }
}

// ---------------------------------------------------------------------------
// Launch
// ---------------------------------------------------------------------------
extern "C" void kernel_launch(void* const* d_in, const int* in_sizes, int n_in,
                              void* d_out, int out_size) {
    const float* x   = (const float*)d_in[0];
    const float* Wq  = (const float*)d_in[1];
    const float* bq  = (const float*)d_in[2];
    const float* Wk  = (const float*)d_in[3];
    const float* bk  = (const float*)d_in[4];
    const float* Wv  = (const float*)d_in[5];
    const float* bv  = (const float*)d_in[6];
    const float* Wo  = (const float*)d_in[7];
    const float* bo  = (const float*)d_in[8];
    const float* W1  = (const float*)d_in[9];
    const float* b1  = (const float*)d_in[10];
    const float* Wm  = (const float*)d_in[11];
    const float* bm  = (const float*)d_in[12];
    const float* W2  = (const float*)d_in[13];
    const float* b2  = (const float*)d_in[14];
    const float* g1  = (const float*)d_in[15];
    const float* be1 = (const float*)d_in[16];
    const float* g2  = (const float*)d_in[17];
    const float* be2 = (const float*)d_in[18];

    static float *ph = nullptr, *phr, *pq, *pk, *pv, *pctx, *px1, *pf1, *pf2, *pfb;
    static float *pwv, *pwo, *pw1, *pwm, *pw2;
    if (ph == nullptr) {
        cudaGetSymbolAddress((void**)&ph,   g_h);
        cudaGetSymbolAddress((void**)&phr,  g_hr);
        cudaGetSymbolAddress((void**)&pq,   g_q);
        cudaGetSymbolAddress((void**)&pk,   g_k);
        cudaGetSymbolAddress((void**)&pv,   g_v);
        cudaGetSymbolAddress((void**)&pctx, g_ctx);
        cudaGetSymbolAddress((void**)&px1,  g_x1);
        cudaGetSymbolAddress((void**)&pf1,  g_f1);
        cudaGetSymbolAddress((void**)&pf2,  g_f2);
        cudaGetSymbolAddress((void**)&pfb,  g_attn_fb);
        cudaGetSymbolAddress((void**)&pwv,  g_wv_r);
        cudaGetSymbolAddress((void**)&pwo,  g_wo_r);
        cudaGetSymbolAddress((void**)&pw1,  g_w1_r);
        cudaGetSymbolAddress((void**)&pwm,  g_wm_r);
        cudaGetSymbolAddress((void**)&pw2,  g_w2_r);
        cudaFuncSetAttribute((const void*)tgemm_nt<0>, cudaFuncAttributeMaxDynamicSharedMemorySize, TG_SMEM);
        cudaFuncSetAttribute((const void*)tgemm_nt<1>, cudaFuncAttributeMaxDynamicSharedMemorySize, TG_SMEM);
        cudaFuncSetAttribute((const void*)tgemm_nt<2>, cudaFuncAttributeMaxDynamicSharedMemorySize, TG_SMEM);
    }

    float* out_x = (float*)d_out;
    long long attn_elems = (long long)B_SZ * H_N * S_LEN * S_LEN;
    long long x_elems = (long long)NROWS * D_DIM;
    float* attn = ((long long)out_size >= x_elems + attn_elems)
                      ? (out_x + x_elems) : pfb;

    // 0. tf32-round the tensor-core weights (rna; idempotent => bit-identical)
    round_kernel<<<512, 256>>>(Wv, pwv, D_DIM * D_DIM / 4);
    round_kernel<<<512, 256>>>(Wo, pwo, D_DIM * D_DIM / 4);
    round_kernel<<<1024, 256>>>(W1, pw1, DF_DIM * D_DIM / 4);
    round_kernel<<<2048, 256>>>(Wm, pwm, DF_DIM * DF_DIM / 4);
    round_kernel<<<1024, 256>>>(W2, pw2, D_DIM * DF_DIM / 4);

    // 1. h = LN(x; g1, be1): unrounded for Q/K (fp32), rounded copy for V
    ln_kernel<<<NROWS, 256>>>(x, g1, be1, ph, phr);

    // 2. Q, K fp32 (protect top-k selection — R15 proved tf32 here fails);
    //    V tf32 tensor cores
    dim3 gQKV(D_DIM / 128, NROWS / 128, 1);
    sgemm_nt<0, false><<<gQKV, 256>>>(ph, Wq, bq, nullptr, pq, D_DIM, D_DIM, D_DIM, D_DIM, 1.0f, 0);
    sgemm_nt<0, false><<<gQKV, 256>>>(ph, Wk, bk, nullptr, pk, D_DIM, D_DIM, D_DIM, D_DIM, 1.0f, 0);
    tgemm_nt<0><<<dim3(D_DIM / 256, NROWS / 128), 256, TG_SMEM>>>(
        phr, pwv, bv, nullptr, pv, D_DIM, D_DIM, D_DIM, D_DIM);

    // 3. scores = Q K^T / 8 (fp32, per head, into attn region)
    dim3 gS(S_LEN / 128, S_LEN / 128, B_SZ * H_N);
    sgemm_nt<0, true><<<gS, 256>>>(pq, pk, nullptr, nullptr, attn,
                                   DKH, D_DIM, D_DIM, S_LEN, 0.125f,
                                   (long)S_LEN * S_LEN);

    // 4. top-k(307) + softmax, in place
    topk_softmax_kernel<<<B_SZ * H_N * S_LEN, 256>>>(attn);

    // 5. ctx = attn @ V (stores tf32-rounded ctx)
    attn_v_kernel<<<dim3(S_LEN / 128, B_SZ * H_N), 256>>>(attn, pv, pctx);

    // 6. x1 = x + ctx @ Wo^T + bo   (tf32)
    tgemm_nt<2><<<dim3(D_DIM / 256, NROWS / 128), 256, TG_SMEM>>>(
        pctx, pwo, bo, x, px1, D_DIM, D_DIM, D_DIM, D_DIM);

    // 7. h2 = LN(x1; g2, be2): rounded only (sole consumer is W1 tf32 GEMM)
    ln_kernel<<<NROWS, 256>>>(px1, g2, be2, nullptr, ph);

    // 8. f1 = gelu(h2 @ W1^T + b1), stored tf32-rounded   (tf32)
    tgemm_nt<1><<<dim3(DF_DIM / 256, NROWS / 128), 256, TG_SMEM>>>(
        ph, pw1, b1, nullptr, pf1, D_DIM, D_DIM, D_DIM, DF_DIM);

    // 9. f2 = gelu(f1 @ Wm^T + bm), stored tf32-rounded   (tf32)
    tgemm_nt<1><<<dim3(DF_DIM / 256, NROWS / 128), 256, TG_SMEM>>>(
        pf1, pwm, bm, nullptr, pf2, DF_DIM, DF_DIM, DF_DIM, DF_DIM);

    // 10. out_x = x1 + f2 @ W2^T + b2   (tf32)
    tgemm_nt<2><<<dim3(D_DIM / 256, NROWS / 128), 256, TG_SMEM>>>(
        pf2, pw2, b2, px1, out_x, DF_DIM, DF_DIM, DF_DIM, D_DIM);
}

// round 17
// speedup vs baseline: 1.1202x; 1.1202x over previous
#include <cuda_runtime.h>
#include <math.h>
#include <stdint.h>

// Problem constants
#define B_SZ   4
#define S_LEN  1024
#define D_DIM  1024
#define H_N    16
#define DKH    64
#define DF_DIM 4096
#define NROWS  (B_SZ * S_LEN)         // 4096
#define TOPK   307                    // int(1024 * 0.3)

// ---------------------------------------------------------------------------
// Scratch (static device globals; no runtime allocation allowed)
// ---------------------------------------------------------------------------
__device__ float g_h  [NROWS * D_DIM];     // LN output (unrounded, for Q/K)
__device__ float g_hr [NROWS * D_DIM];     // tf32-rounded LN output
__device__ float g_q  [NROWS * D_DIM];
__device__ float g_k  [NROWS * D_DIM];
__device__ float g_v  [NROWS * D_DIM];
__device__ float g_ctx[NROWS * D_DIM];
__device__ float g_x1 [NROWS * D_DIM];
__device__ float g_f1 [NROWS * DF_DIM];
__device__ float g_f2 [NROWS * DF_DIM];
__device__ float g_wv_r[D_DIM * D_DIM];
__device__ float g_wo_r[D_DIM * D_DIM];
__device__ float g_w1_r[DF_DIM * D_DIM];
__device__ float g_wm_r[DF_DIM * DF_DIM];
__device__ float g_w2_r[D_DIM * DF_DIM];
__device__ float g_attn_fb[B_SZ * H_N * S_LEN * S_LEN];

__device__ __forceinline__ float gelu_f(float x) {
    return 0.5f * x * (1.0f + erff(x * 0.70710678118654752440f));
}

__device__ __forceinline__ float tf32f(float f) {
    unsigned r;
    asm("cvt.rna.tf32.f32 %0, %1;" : "=r"(r) : "f"(f));
    return __uint_as_float(r);
}

__device__ __forceinline__ unsigned tf32u(float f) {
    unsigned r;
    asm("cvt.rna.tf32.f32 %0, %1;" : "=r"(r) : "f"(f));
    return r;
}

// ---------------------------------------------------------------------------
// Elementwise tf32 rounding (weights pre-pass). n multiple of 4.
// ---------------------------------------------------------------------------
__global__ __launch_bounds__(256) void round_kernel(const float* __restrict__ src,
                                                    float* __restrict__ dst, int n4) {
    int i = blockIdx.x * 256 + threadIdx.x;
    int stride = gridDim.x * 256;
    for (; i < n4; i += stride) {
        float4 v = ((const float4*)src)[i];
        v.x = tf32f(v.x); v.y = tf32f(v.y);
        v.z = tf32f(v.z); v.w = tf32f(v.w);
        ((float4*)dst)[i] = v;
    }
}

// ---------------------------------------------------------------------------
// LayerNorm: one block per row of 1024. Optional unrounded and tf32-rounded
// outputs (either may be null).
// ---------------------------------------------------------------------------
__global__ __launch_bounds__(256) void ln_kernel(const float* __restrict__ x,
                                                 const float* __restrict__ g,
                                                 const float* __restrict__ b,
                                                 float* __restrict__ out,
                                                 float* __restrict__ out_r) {
    __shared__ float rs[256], rq[256];
    int row = blockIdx.x, tid = threadIdx.x;
    const float4* px = (const float4*)(x + (size_t)row * D_DIM);
    float4 v = px[tid];
    float s = v.x + v.y + v.z + v.w;
    float q = v.x*v.x + v.y*v.y + v.z*v.z + v.w*v.w;
    rs[tid] = s; rq[tid] = q;
    __syncthreads();
    for (int st = 128; st > 0; st >>= 1) {
        if (tid < st) { rs[tid] += rs[tid+st]; rq[tid] += rq[tid+st]; }
        __syncthreads();
    }
    float mu  = rs[0] * (1.0f / D_DIM);
    float var = rq[0] * (1.0f / D_DIM) - mu * mu;
    float rstd = rsqrtf(var + 1e-5f);
    float4 gg = ((const float4*)g)[tid];
    float4 bb = ((const float4*)b)[tid];
    float4 o;
    o.x = (v.x - mu) * rstd * gg.x + bb.x;
    o.y = (v.y - mu) * rstd * gg.y + bb.y;
    o.z = (v.z - mu) * rstd * gg.z + bb.z;
    o.w = (v.w - mu) * rstd * gg.w + bb.w;
    if (out)
        ((float4*)(out + (size_t)row * D_DIM))[tid] = o;
    if (out_r) {
        float4 r;
        r.x = tf32f(o.x); r.y = tf32f(o.y);
        r.z = tf32f(o.z); r.w = tf32f(o.w);
        ((float4*)(out_r + (size_t)row * D_DIM))[tid] = r;
    }
}

// ---------------------------------------------------------------------------
// fp32 SGEMM NT (Q, K, per-head scores — protects top-k selection; R15 proved
// tf32 here flips selections and blows up the attn output error)
// ---------------------------------------------------------------------------
template<int MODE, bool HEAD>
__global__ __launch_bounds__(256) void sgemm_nt(const float* __restrict__ A,
                                                const float* __restrict__ B,
                                                const float* __restrict__ bias,
                                                const float* __restrict__ R,
                                                float* __restrict__ C,
                                                int K, int lda, int ldb, int ldc,
                                                float alpha, long strideC) {
    __shared__ float As[2][16][132];
    __shared__ float Bs[2][16][132];
    int tid = threadIdx.x;

    const float* Ab = A + (size_t)blockIdx.y * 128 * lda;
    const float* Bb = B + (size_t)blockIdx.x * 128 * ldb;
    float* Cb = C;
    if (HEAD) {
        int z = blockIdx.z;
        size_t off = (size_t)(z >> 4) * (S_LEN * D_DIM) + (size_t)(z & 15) * DKH;
        Ab += off; Bb += off;
        Cb += (size_t)z * strideC;
    }

    int tx = tid & 15, ty = tid >> 4;
    int lr = tid >> 2;
    int lc = (tid & 3) << 2;

    float acc[8][8];
#pragma unroll
    for (int i = 0; i < 8; i++)
#pragma unroll
        for (int j = 0; j < 8; j++) acc[i][j] = 0.0f;

#pragma unroll
    for (int r = 0; r < 2; r++) {
        int row = lr + r * 64;
        float4 va = *(const float4*)(Ab + (size_t)row * lda + lc);
        As[0][lc+0][row] = va.x; As[0][lc+1][row] = va.y;
        As[0][lc+2][row] = va.z; As[0][lc+3][row] = va.w;
        float4 vb = *(const float4*)(Bb + (size_t)row * ldb + lc);
        Bs[0][lc+0][row] = vb.x; Bs[0][lc+1][row] = vb.y;
        Bs[0][lc+2][row] = vb.z; Bs[0][lc+3][row] = vb.w;
    }
    __syncthreads();

    int buf = 0;
    for (int k0 = 0; k0 < K; k0 += 16) {
        float4 pa[2], pb[2];
        bool more = (k0 + 16 < K);
        if (more) {
#pragma unroll
            for (int r = 0; r < 2; r++) {
                int row = lr + r * 64;
                pa[r] = *(const float4*)(Ab + (size_t)row * lda + (k0 + 16) + lc);
                pb[r] = *(const float4*)(Bb + (size_t)row * ldb + (k0 + 16) + lc);
            }
        }
#pragma unroll
        for (int k = 0; k < 16; k++) {
            float4 a0 = *(const float4*)(&As[buf][k][ty * 8]);
            float4 a1 = *(const float4*)(&As[buf][k][ty * 8 + 4]);
            float4 b0 = *(const float4*)(&Bs[buf][k][tx * 8]);
            float4 b1 = *(const float4*)(&Bs[buf][k][tx * 8 + 4]);
            float ra[8] = {a0.x, a0.y, a0.z, a0.w, a1.x, a1.y, a1.z, a1.w};
            float rb[8] = {b0.x, b0.y, b0.z, b0.w, b1.x, b1.y, b1.z, b1.w};
#pragma unroll
            for (int i = 0; i < 8; i++)
#pragma unroll
                for (int j = 0; j < 8; j++)
                    acc[i][j] = fmaf(ra[i], rb[j], acc[i][j]);
        }
        if (more) {
            int nb = buf ^ 1;
#pragma unroll
            for (int r = 0; r < 2; r++) {
                int row = lr + r * 64;
                As[nb][lc+0][row] = pa[r].x; As[nb][lc+1][row] = pa[r].y;
                As[nb][lc+2][row] = pa[r].z; As[nb][lc+3][row] = pa[r].w;
                Bs[nb][lc+0][row] = pb[r].x; Bs[nb][lc+1][row] = pb[r].y;
                Bs[nb][lc+2][row] = pb[r].z; Bs[nb][lc+3][row] = pb[r].w;
            }
        }
        __syncthreads();
        buf ^= 1;
    }

#pragma unroll
    for (int i = 0; i < 8; i++) {
        size_t m = (size_t)blockIdx.y * 128 + ty * 8 + i;
#pragma unroll
        for (int j4 = 0; j4 < 8; j4 += 4) {
            int n = blockIdx.x * 128 + tx * 8 + j4;
            float4 v;
            v.x = acc[i][j4+0] * alpha;
            v.y = acc[i][j4+1] * alpha;
            v.z = acc[i][j4+2] * alpha;
            v.w = acc[i][j4+3] * alpha;
            if (bias != nullptr) {
                float4 bb = *(const float4*)(bias + n);
                v.x += bb.x; v.y += bb.y; v.z += bb.z; v.w += bb.w;
            }
            if (MODE == 1) {
                v.x = gelu_f(v.x); v.y = gelu_f(v.y);
                v.z = gelu_f(v.z); v.w = gelu_f(v.w);
            }
            if (MODE == 2) {
                float4 rr = *(const float4*)(R + m * ldc + n);
                v.x += rr.x; v.y += rr.y; v.z += rr.z; v.w += rr.w;
            }
            *(float4*)(Cb + m * ldc + n) = v;
        }
    }
}

// ---------------------------------------------------------------------------
// TF32 tensor-core GEMM NT, cp.async 3-stage pipeline  (R14 config: 128x128x32,
// 2 CTAs/SM — R16 proved 128x256 @ 1 CTA/SM regresses).
// Inputs A and B MUST already be tf32-rounded.
// MODE: 0 plain(+bias), 1 GELU+bias stored tf32-rounded, 2 +bias +residual R,
//       3 +bias stored tf32-rounded
// ---------------------------------------------------------------------------
#define TG_SSZ   (128 * 32)            // floats per matrix per stage
#define TG_STAGE (2 * TG_SSZ)          // floats per stage (A+B)
#define TG_SMEM  (3 * TG_STAGE * 4)    // bytes (96 KB)

template<int MODE>
__global__ __launch_bounds__(256, 2) void tgemm_nt(const float* __restrict__ A,
                                                   const float* __restrict__ B,
                                                   const float* __restrict__ bias,
                                                   const float* __restrict__ R,
                                                   float* __restrict__ C,
                                                   int K, int lda, int ldb, int ldc) {
    extern __shared__ float sm[];

    int tid  = threadIdx.x;
    int lane = tid & 31;
    int warp = tid >> 5;
    int wm   = warp >> 2;
    int wn   = warp & 3;
    int rowi = lane >> 2;
    int kq   = lane & 3;

    const float* Ab = A + (size_t)blockIdx.y * 128 * lda;
    const float* Bb = B + (size_t)blockIdx.x * 128 * ldb;

    int lr = tid >> 3;   // 0..31 : load row base
    int lc = tid & 7;    // chunk 0..7

    int aoff[4], boff[4];
#pragma unroll
    for (int mt = 0; mt < 4; mt++) aoff[mt] = (wm * 64 + mt * 16 + rowi) * 32 + kq;
#pragma unroll
    for (int nt = 0; nt < 4; nt++) boff[nt] = (wn * 32 + nt * 8 + rowi) * 32 + kq;

    float acc[4][4][4];
#pragma unroll
    for (int mt = 0; mt < 4; mt++)
#pragma unroll
        for (int nt = 0; nt < 4; nt++)
#pragma unroll
            for (int r = 0; r < 4; r++) acc[mt][nt][r] = 0.0f;

    auto issue = [&](int kt, int st) {
        float* sA = sm + st * TG_STAGE;
        float* sB = sA + TG_SSZ;
#pragma unroll
        for (int i = 0; i < 4; i++) {
            int row  = lr + i * 32;
            int sidx = row * 32 + ((lc ^ (row & 7)) << 2);
            const float* gA = Ab + (size_t)row * lda + kt * 32 + lc * 4;
            const float* gB = Bb + (size_t)row * ldb + kt * 32 + lc * 4;
            unsigned sa = (unsigned)__cvta_generic_to_shared(sA + sidx);
            unsigned sb = (unsigned)__cvta_generic_to_shared(sB + sidx);
            asm volatile("cp.async.cg.shared.global [%0], [%1], 16;"
                         :: "r"(sa), "l"(gA));
            asm volatile("cp.async.cg.shared.global [%0], [%1], 16;"
                         :: "r"(sb), "l"(gB));
        }
        asm volatile("cp.async.commit_group;");
    };

    int NT = K >> 5;
    issue(0, 0);
    issue(1, 1);

    for (int it = 0; it < NT; it++) {
        if (it + 1 < NT) asm volatile("cp.async.wait_group 1;");
        else             asm volatile("cp.async.wait_group 0;");
        __syncthreads();
        if (it + 2 < NT) issue(it + 2, (it + 2) % 3);

        const unsigned* sA = (const unsigned*)(sm + (it % 3) * TG_STAGE);
        const unsigned* sB = sA + TG_SSZ;

#pragma unroll
        for (int g = 0; g < 4; g++) {
            int sw0 = (((g << 1))     ^ rowi) << 2;
            int sw1 = (((g << 1) | 1) ^ rowi) << 2;
            unsigned af[4][4];
#pragma unroll
            for (int mt = 0; mt < 4; mt++) {
                af[mt][0] = sA[aoff[mt] + sw0];
                af[mt][1] = sA[aoff[mt] + 256 + sw0];
                af[mt][2] = sA[aoff[mt] + sw1];
                af[mt][3] = sA[aoff[mt] + 256 + sw1];
            }
            unsigned bf[4][2];
#pragma unroll
            for (int nt = 0; nt < 4; nt++) {
                bf[nt][0] = sB[boff[nt] + sw0];
                bf[nt][1] = sB[boff[nt] + sw1];
            }
#pragma unroll
            for (int mt = 0; mt < 4; mt++)
#pragma unroll
                for (int nt = 0; nt < 4; nt++)
                    asm volatile(
                        "mma.sync.aligned.m16n8k8.row.col.f32.tf32.tf32.f32 "
                        "{%0,%1,%2,%3}, {%4,%5,%6,%7}, {%8,%9}, {%0,%1,%2,%3};"
                        : "+f"(acc[mt][nt][0]), "+f"(acc[mt][nt][1]),
                          "+f"(acc[mt][nt][2]), "+f"(acc[mt][nt][3])
                        : "r"(af[mt][0]), "r"(af[mt][1]), "r"(af[mt][2]), "r"(af[mt][3]),
                          "r"(bf[nt][0]), "r"(bf[nt][1]));
        }
    }

    // ---- epilogue ----
#pragma unroll
    for (int mt = 0; mt < 4; mt++) {
#pragma unroll
        for (int rr = 0; rr < 2; rr++) {
            size_t m = (size_t)blockIdx.y * 128 + wm * 64 + mt * 16 + rowi + rr * 8;
#pragma unroll
            for (int nt = 0; nt < 4; nt++) {
                int n = blockIdx.x * 128 + wn * 32 + nt * 8 + kq * 2;
                float v0 = acc[mt][nt][rr * 2 + 0];
                float v1 = acc[mt][nt][rr * 2 + 1];
                if (bias != nullptr) {
                    float2 bb = *(const float2*)(bias + n);
                    v0 += bb.x; v1 += bb.y;
                }
                if (MODE == 1) {
                    v0 = tf32f(gelu_f(v0)); v1 = tf32f(gelu_f(v1));
                }
                if (MODE == 2) {
                    float2 rv = *(const float2*)(R + m * ldc + n);
                    v0 += rv.x; v1 += rv.y;
                }
                if (MODE == 3) {
                    v0 = tf32f(v0); v1 = tf32f(v1);
                }
                float2 o; o.x = v0; o.y = v1;
                *(float2*)(C + m * ldc + n) = o;
            }
        }
    }
}

// ---------------------------------------------------------------------------
// Exact top-k(307) + softmax per row of 1024, in place.
// ---------------------------------------------------------------------------
__global__ __launch_bounds__(256) void topk_softmax_kernel(float* __restrict__ attn) {
    __shared__ float vals[1024];
    __shared__ unsigned int keys[1024];
    __shared__ unsigned int hist[256];
    __shared__ unsigned int sufs[256];
    __shared__ unsigned int wsum[8];
    __shared__ int tie_idx[1024];
    __shared__ unsigned char keep[1024];
    __shared__ float red[256];
    __shared__ int s_bsel, s_rsub, s_tcnt;

    int tid  = threadIdx.x;
    int lane = tid & 31;
    int wid  = tid >> 5;
    float* p = attn + (size_t)blockIdx.x * 1024;

    for (int i = tid; i < 1024; i += 256) {
        float v = p[i];
        vals[i] = v;
        unsigned u = __float_as_uint(v);
        keys[i] = (u & 0x80000000u) ? ~u : (u | 0x80000000u);
    }
    __syncthreads();

    unsigned prefix = 0u, pmask = 0u;
    int r = TOPK;
    for (int shift = 24; shift >= 0; shift -= 8) {
        hist[tid] = 0u;
        __syncthreads();
        for (int i = tid; i < 1024; i += 256) {
            unsigned kk = keys[i];
            if ((kk & pmask) == prefix) atomicAdd(&hist[(kk >> shift) & 0xFFu], 1u);
        }
        __syncthreads();

        unsigned v = hist[tid];
#pragma unroll
        for (int d = 1; d < 32; d <<= 1) {
            unsigned t = __shfl_down_sync(0xFFFFFFFFu, v, d);
            if (lane + d < 32) v += t;
        }
        if (lane == 0) wsum[wid] = v;
        __syncthreads();
        unsigned add = 0;
#pragma unroll
        for (int w = 0; w < 8; w++)
            if (w > wid) add += wsum[w];
        v += add;
        sufs[tid] = v;
        __syncthreads();

        unsigned cum  = sufs[tid];
        unsigned cumn = (tid < 255) ? sufs[tid + 1] : 0u;
        if ((int)cum >= r && (int)cumn < r) { s_bsel = tid; s_rsub = (int)cumn; }
        __syncthreads();
        prefix |= ((unsigned)s_bsel) << shift;
        pmask  |= (0xFFu << shift);
        r -= s_rsub;
        __syncthreads();
    }
    unsigned tk = prefix;

    if (tid == 0) s_tcnt = 0;
    __syncthreads();
    for (int i = tid; i < 1024; i += 256) {
        unsigned kk = keys[i];
        unsigned char kp = (kk > tk) ? (unsigned char)1 : (unsigned char)0;
        if (kk == tk) { int pos = atomicAdd(&s_tcnt, 1); tie_idx[pos] = i; }
        keep[i] = kp;
    }
    __syncthreads();
    int tc = s_tcnt;
    for (int j = tid; j < tc; j += 256) {
        int myi = tie_idx[j];
        int rank = 0;
        for (int l = 0; l < tc; l++) rank += (tie_idx[l] < myi) ? 1 : 0;
        if (rank < r) keep[myi] = 1;
    }
    __syncthreads();

    float lm = -3.4e38f;
    for (int i = tid; i < 1024; i += 256)
        if (keep[i]) lm = fmaxf(lm, vals[i]);
    red[tid] = lm;
    __syncthreads();
    for (int st = 128; st > 0; st >>= 1) {
        if (tid < st) red[tid] = fmaxf(red[tid], red[tid + st]);
        __syncthreads();
    }
    float mx = red[0];
    __syncthreads();

    float ls = 0.0f;
    for (int i = tid; i < 1024; i += 256) {
        float e = keep[i] ? expf(vals[i] - mx) : 0.0f;
        vals[i] = e;
        ls += e;
    }
    red[tid] = ls;
    __syncthreads();
    for (int st = 128; st > 0; st >>= 1) {
        if (tid < st) red[tid] += red[tid + st];
        __syncthreads();
    }
    float inv = 1.0f / red[0];
    __syncthreads();
    for (int i = tid; i < 1024; i += 256) p[i] = vals[i] * inv;
}

// ---------------------------------------------------------------------------
// ctx = attn @ V per head — tf32 tensor cores.
// Block 128(q) x 64(dk), K-loop over s in steps of 32, double-buffered.
// attn tile: cp.async, XOR-swizzled rows of 32 floats; A fragments get
// cvt.rna (attn must stay exact in d_out). V is pre-rounded (MODE 3 producer),
// staged [32][68] (B-fragment loads 2-way conflicted max — acceptable).
// 8 warps as 4m x 2n, warp tile 32x32. ctx stored tf32-rounded (feeds Wo).
// Affects output 0 only — never the top-k selection path.
// ---------------------------------------------------------------------------
#define AV_ASZ   (128 * 32)
#define AV_VSZ   (32 * 68)
#define AV_STAGE (AV_ASZ + AV_VSZ)        // 6272 floats
#define AV_SMEM  (2 * AV_STAGE * 4)       // 50176 bytes

__global__ __launch_bounds__(256) void attn_v_tc(const float* __restrict__ attn,
                                                 const float* __restrict__ V,
                                                 float* __restrict__ ctx) {
    extern __shared__ float sm[];
    int tid  = threadIdx.x;
    int lane = tid & 31;
    int warp = tid >> 5;
    int wm   = warp >> 1;      // 0..3 -> 32-row band
    int wn   = warp & 1;       // 0..1 -> 32-col band
    int rowi = lane >> 2;
    int kq   = lane & 3;

    int z = blockIdx.y;
    int b = z >> 4, h = z & 15;
    const float* Ab = attn + (size_t)z * (S_LEN * S_LEN) + (size_t)blockIdx.x * 128 * S_LEN;
    const float* Vb = V + (size_t)b * (S_LEN * D_DIM) + h * DKH;

    int lr = tid >> 3;   // 0..31
    int lc = tid & 7;    // chunk 0..7

    int aoff[2], noff[4];
#pragma unroll
    for (int mt = 0; mt < 2; mt++) aoff[mt] = (wm * 32 + mt * 16 + rowi) * 32 + kq;
#pragma unroll
    for (int nt = 0; nt < 4; nt++) noff[nt] = wn * 32 + nt * 8 + rowi;

    float acc[2][4][4];
#pragma unroll
    for (int mt = 0; mt < 2; mt++)
#pragma unroll
        for (int nt = 0; nt < 4; nt++)
#pragma unroll
            for (int r = 0; r < 4; r++) acc[mt][nt][r] = 0.0f;

    // attn tile loader (cp.async, swizzled like tgemm)
    auto issueA = [&](int kt, int st) {
        float* sA = sm + st * AV_STAGE;
#pragma unroll
        for (int i = 0; i < 4; i++) {
            int row  = lr + i * 32;
            int sidx = row * 32 + ((lc ^ (row & 7)) << 2);
            const float* gA = Ab + (size_t)row * S_LEN + kt * 32 + lc * 4;
            unsigned sa = (unsigned)__cvta_generic_to_shared(sA + sidx);
            asm volatile("cp.async.cg.shared.global [%0], [%1], 16;"
                         :: "r"(sa), "l"(gA));
        }
        asm volatile("cp.async.commit_group;");
    };

    int vrow0 = tid >> 4;            // 0..15
    int vn    = (tid & 15) << 2;     // 0,4,..,60

    float4 va, vb2;
    auto ldgV = [&](int kt) {
        va  = *(const float4*)(Vb + (size_t)(kt * 32 + vrow0)      * D_DIM + vn);
        vb2 = *(const float4*)(Vb + (size_t)(kt * 32 + vrow0 + 16) * D_DIM + vn);
    };
    auto stsV = [&](int st) {
        float* sV = sm + st * AV_STAGE + AV_ASZ;
        *(float4*)(sV + vrow0 * 68 + vn)        = va;
        *(float4*)(sV + (vrow0 + 16) * 68 + vn) = vb2;
    };

    // preload stage 0
    issueA(0, 0);
    ldgV(0);
    stsV(0);
    asm volatile("cp.async.wait_group 0;");
    __syncthreads();

    int buf = 0;
    for (int it = 0; it < S_LEN / 32; it++) {
        bool more = (it + 1 < S_LEN / 32);
        if (more) {
            issueA(it + 1, buf ^ 1);
            ldgV(it + 1);
        }

        const float* sA = sm + buf * AV_STAGE;
        const unsigned* sV = (const unsigned*)(sm + buf * AV_STAGE + AV_ASZ);

#pragma unroll
        for (int g = 0; g < 4; g++) {
            int sw0 = (((g << 1))     ^ rowi) << 2;
            int sw1 = (((g << 1) | 1) ^ rowi) << 2;
            unsigned af[2][4];
#pragma unroll
            for (int mt = 0; mt < 2; mt++) {
                af[mt][0] = tf32u(sA[aoff[mt] + sw0]);
                af[mt][1] = tf32u(sA[aoff[mt] + 256 + sw0]);
                af[mt][2] = tf32u(sA[aoff[mt] + sw1]);
                af[mt][3] = tf32u(sA[aoff[mt] + 256 + sw1]);
            }
            unsigned bf[4][2];
#pragma unroll
            for (int nt = 0; nt < 4; nt++) {
                bf[nt][0] = sV[(8 * g + kq)     * 68 + noff[nt]];
                bf[nt][1] = sV[(8 * g + 4 + kq) * 68 + noff[nt]];
            }
#pragma unroll
            for (int mt = 0; mt < 2; mt++)
#pragma unroll
                for (int nt = 0; nt < 4; nt++)
                    asm volatile(
                        "mma.sync.aligned.m16n8k8.row.col.f32.tf32.tf32.f32 "
                        "{%0,%1,%2,%3}, {%4,%5,%6,%7}, {%8,%9}, {%0,%1,%2,%3};"
                        : "+f"(acc[mt][nt][0]), "+f"(acc[mt][nt][1]),
                          "+f"(acc[mt][nt][2]), "+f"(acc[mt][nt][3])
                        : "r"(af[mt][0]), "r"(af[mt][1]), "r"(af[mt][2]), "r"(af[mt][3]),
                          "r"(bf[nt][0]), "r"(bf[nt][1]));
        }

        if (more) stsV(buf ^ 1);
        asm volatile("cp.async.wait_group 0;");
        __syncthreads();
        buf ^= 1;
    }

    // epilogue: ctx stored tf32-rounded (sole consumer: Wo tf32 GEMM)
#pragma unroll
    for (int mt = 0; mt < 2; mt++) {
#pragma unroll
        for (int rr = 0; rr < 2; rr++) {
            size_t m = (size_t)b * S_LEN + (size_t)blockIdx.x * 128
                     + wm * 32 + mt * 16 + rowi + rr * 8;
#pragma unroll
            for (int nt = 0; nt < 4; nt++) {
                int n = h * DKH + wn * 32 + nt * 8 + kq * 2;
                float2 o;
                o.x = tf32f(acc[mt][nt][rr * 2 + 0]);
                o.y = tf32f(acc[mt][nt][rr * 2 + 1]);
                *(float2*)(ctx + m * D_DIM + n) = o;
            }
        }
    }
}

// ---------------------------------------------------------------------------
// Launch
// ---------------------------------------------------------------------------
extern "C" void kernel_launch(void* const* d_in, const int* in_sizes, int n_in,
                              void* d_out, int out_size) {
    const float* x   = (const float*)d_in[0];
    const float* Wq  = (const float*)d_in[1];
    const float* bq  = (const float*)d_in[2];
    const float* Wk  = (const float*)d_in[3];
    const float* bk  = (const float*)d_in[4];
    const float* Wv  = (const float*)d_in[5];
    const float* bv  = (const float*)d_in[6];
    const float* Wo  = (const float*)d_in[7];
    const float* bo  = (const float*)d_in[8];
    const float* W1  = (const float*)d_in[9];
    const float* b1  = (const float*)d_in[10];
    const float* Wm  = (const float*)d_in[11];
    const float* bm  = (const float*)d_in[12];
    const float* W2  = (const float*)d_in[13];
    const float* b2  = (const float*)d_in[14];
    const float* g1  = (const float*)d_in[15];
    const float* be1 = (const float*)d_in[16];
    const float* g2  = (const float*)d_in[17];
    const float* be2 = (const float*)d_in[18];

    static float *ph = nullptr, *phr, *pq, *pk, *pv, *pctx, *px1, *pf1, *pf2, *pfb;
    static float *pwv, *pwo, *pw1, *pwm, *pw2;
    if (ph == nullptr) {
        cudaGetSymbolAddress((void**)&ph,   g_h);
        cudaGetSymbolAddress((void**)&phr,  g_hr);
        cudaGetSymbolAddress((void**)&pq,   g_q);
        cudaGetSymbolAddress((void**)&pk,   g_k);
        cudaGetSymbolAddress((void**)&pv,   g_v);
        cudaGetSymbolAddress((void**)&pctx, g_ctx);
        cudaGetSymbolAddress((void**)&px1,  g_x1);
        cudaGetSymbolAddress((void**)&pf1,  g_f1);
        cudaGetSymbolAddress((void**)&pf2,  g_f2);
        cudaGetSymbolAddress((void**)&pfb,  g_attn_fb);
        cudaGetSymbolAddress((void**)&pwv,  g_wv_r);
        cudaGetSymbolAddress((void**)&pwo,  g_wo_r);
        cudaGetSymbolAddress((void**)&pw1,  g_w1_r);
        cudaGetSymbolAddress((void**)&pwm,  g_wm_r);
        cudaGetSymbolAddress((void**)&pw2,  g_w2_r);
        cudaFuncSetAttribute(tgemm_nt<0>, cudaFuncAttributeMaxDynamicSharedMemorySize, TG_SMEM);
        cudaFuncSetAttribute(tgemm_nt<1>, cudaFuncAttributeMaxDynamicSharedMemorySize, TG_SMEM);
        cudaFuncSetAttribute(tgemm_nt<2>, cudaFuncAttributeMaxDynamicSharedMemorySize, TG_SMEM);
        cudaFuncSetAttribute(tgemm_nt<3>, cudaFuncAttributeMaxDynamicSharedMemorySize, TG_SMEM);
        cudaFuncSetAttribute(attn_v_tc,  cudaFuncAttributeMaxDynamicSharedMemorySize, AV_SMEM);
    }

    float* out_x = (float*)d_out;
    long long attn_elems = (long long)B_SZ * H_N * S_LEN * S_LEN;
    long long x_elems = (long long)NROWS * D_DIM;
    float* attn = ((long long)out_size >= x_elems + attn_elems)
                      ? (out_x + x_elems) : pfb;

    // 0. tf32-round the tensor-core weights (rna; idempotent => bit-identical)
    round_kernel<<<512, 256>>>(Wv, pwv, D_DIM * D_DIM / 4);
    round_kernel<<<512, 256>>>(Wo, pwo, D_DIM * D_DIM / 4);
    round_kernel<<<1024, 256>>>(W1, pw1, DF_DIM * D_DIM / 4);
    round_kernel<<<2048, 256>>>(Wm, pwm, DF_DIM * DF_DIM / 4);
    round_kernel<<<1024, 256>>>(W2, pw2, D_DIM * DF_DIM / 4);

    // 1. h = LN(x; g1, be1): unrounded for Q/K (fp32), rounded copy for V
    ln_kernel<<<NROWS, 256>>>(x, g1, be1, ph, phr);

    // 2. Q, K fp32 (protect top-k selection); V tf32 (stored rounded for attn_v)
    dim3 gQKV(D_DIM / 128, NROWS / 128, 1);
    sgemm_nt<0, false><<<gQKV, 256>>>(ph, Wq, bq, nullptr, pq, D_DIM, D_DIM, D_DIM, D_DIM, 1.0f, 0);
    sgemm_nt<0, false><<<gQKV, 256>>>(ph, Wk, bk, nullptr, pk, D_DIM, D_DIM, D_DIM, D_DIM, 1.0f, 0);
    tgemm_nt<3><<<gQKV, 256, TG_SMEM>>>(phr, pwv, bv, nullptr, pv, D_DIM, D_DIM, D_DIM, D_DIM);

    // 3. scores = Q K^T / 8 (fp32, per head, into attn region)
    dim3 gS(S_LEN / 128, S_LEN / 128, B_SZ * H_N);
    sgemm_nt<0, true><<<gS, 256>>>(pq, pk, nullptr, nullptr, attn,
                                   DKH, D_DIM, D_DIM, S_LEN, 0.125f,
                                   (long)S_LEN * S_LEN);

    // 4. top-k(307) + softmax, in place
    topk_softmax_kernel<<<B_SZ * H_N * S_LEN, 256>>>(attn);

    // 5. ctx = attn @ V (tf32 tensor cores; ctx stored rounded)
    attn_v_tc<<<dim3(S_LEN / 128, B_SZ * H_N), 256, AV_SMEM>>>(attn, pv, pctx);

    // 6. x1 = x + ctx @ Wo^T + bo   (tf32)
    tgemm_nt<2><<<dim3(D_DIM / 128, NROWS / 128), 256, TG_SMEM>>>(
        pctx, pwo, bo, x, px1, D_DIM, D_DIM, D_DIM, D_DIM);

    // 7. h2 = LN(x1; g2, be2): rounded only (sole consumer is W1 tf32 GEMM)
    ln_kernel<<<NROWS, 256>>>(px1, g2, be2, nullptr, ph);

    // 8. f1 = gelu(h2 @ W1^T + b1), stored tf32-rounded   (tf32)
    tgemm_nt<1><<<dim3(DF_DIM / 128, NROWS / 128), 256, TG_SMEM>>>(
        ph, pw1, b1, nullptr, pf1, D_DIM, D_DIM, D_DIM, DF_DIM);

    // 9. f2 = gelu(f1 @ Wm^T + bm), stored tf32-rounded   (tf32)
    tgemm_nt<1><<<dim3(DF_DIM / 128, NROWS / 128), 256, TG_SMEM>>>(
        pf1, pwm, bm, nullptr, pf2, DF_DIM, DF_DIM, DF_DIM, DF_DIM);

    // 10. out_x = x1 + f2 @ W2^T + b2   (tf32)
    tgemm_nt<2><<<dim3(D_DIM / 128, NROWS / 128), 256, TG_SMEM>>>(
        pf2, pw2, b2, px1, out_x, DF_DIM, DF_DIM, DF_DIM, D_DIM);
}